// round 3
// baseline (speedup 1.0000x reference)
#include <cuda_runtime.h>

#define D 128
#define MAX_N 100000
#define MAX_E 1600000
#define WP2 129   // padded W-pair row stride (float2 units) per k2 row

typedef unsigned long long ull;

// Scratch (device globals — no allocations allowed)
__device__ float g_h[(size_t)MAX_N * D];     // normalized h rows
__device__ float g_total[D];
__device__ int   g_cnt[MAX_N];               // degrees, then fill cursor
__device__ int   g_off[MAX_N + 1];           // CSR offsets
__device__ int   g_eidx[MAX_E];              // src ids bucketed by dst
__device__ int   g_bsum[1024];               // scan block sums

// ---------------------------------------------------------------------------
__global__ void k_init(int N) {
    int i = blockIdx.x * blockDim.x + threadIdx.x;
    if (i < N) g_cnt[i] = 0;
    if (i < D) g_total[i] = 0.f;
}

// column sums: total[c] = sum_r feat[r][c]
__global__ void k_total(const float* __restrict__ feat, int N) {
    int c = threadIdx.x;
    float s = 0.f;
    for (int r = blockIdx.x; r < N; r += gridDim.x)
        s += feat[(size_t)r * D + c];
    atomicAdd(&g_total[c], s);
}

__global__ void k_degree(const int* __restrict__ dst, int E) {
    int e = blockIdx.x * blockDim.x + threadIdx.x;
    if (e < E) atomicAdd(&g_cnt[dst[e]], 1);
}

// scan1: per-1024-chunk sums
__global__ void k_scan1(int N) {
    __shared__ int ss[256];
    int base = blockIdx.x * 1024;
    int t = threadIdx.x;
    int s = 0;
    #pragma unroll
    for (int j = 0; j < 4; j++) {
        int i = base + t + j * 256;
        if (i < N) s += g_cnt[i];
    }
    ss[t] = s; __syncthreads();
    for (int o = 128; o; o >>= 1) { if (t < o) ss[t] += ss[t + o]; __syncthreads(); }
    if (t == 0) g_bsum[blockIdx.x] = ss[0];
}

// scan2: exclusive scan of block sums, plus g_off[N] = E
__global__ void k_scan2(int SB, int E, int N) {
    __shared__ int ss[1024];
    int t = threadIdx.x;
    for (int i = t; i < SB; i += blockDim.x) ss[i] = g_bsum[i];
    __syncthreads();
    if (t == 0) {
        int run = 0;
        for (int i = 0; i < SB; i++) { int v = ss[i]; ss[i] = run; run += v; }
        g_off[N] = E;
    }
    __syncthreads();
    for (int i = t; i < SB; i += blockDim.x) g_bsum[i] = ss[i];
}

// scan3: per-chunk exclusive scan + global base -> g_off, cursor init
__global__ void k_scan3(int N) {
    __shared__ int ss[256];
    int base = blockIdx.x * 1024;
    int t = threadIdx.x;
    int c[4]; int s = 0;
    #pragma unroll
    for (int j = 0; j < 4; j++) {
        int i = base + t * 4 + j;
        c[j] = (i < N) ? g_cnt[i] : 0;
        s += c[j];
    }
    ss[t] = s; __syncthreads();
    for (int o = 1; o < 256; o <<= 1) {
        int v = (t >= o) ? ss[t - o] : 0;
        __syncthreads();
        ss[t] += v;
        __syncthreads();
    }
    int run = g_bsum[blockIdx.x] + (ss[t] - s);
    #pragma unroll
    for (int j = 0; j < 4; j++) {
        int i = base + t * 4 + j;
        if (i < N) { g_off[i] = run; g_cnt[i] = run; }
        run += c[j];
    }
}

__global__ void k_fill(const int* __restrict__ src, const int* __restrict__ dst, int E) {
    int e = blockIdx.x * blockDim.x + threadIdx.x;
    if (e < E) {
        int pos = atomicAdd(&g_cnt[dst[e]], 1);
        g_eidx[pos] = src[e];
    }
}

// ---------------------------------------------------------------------------
// Gather + subtract + L2-normalize, fused. One warp per dst node.
// ---------------------------------------------------------------------------
__global__ void k_gather(const float* __restrict__ feat, int N) {
    int wid = (blockIdx.x * blockDim.x + threadIdx.x) >> 5;
    if (wid >= N) return;
    int lane = threadIdx.x & 31;
    int beg = g_off[wid], end = g_off[wid + 1];
    const float4* fp = reinterpret_cast<const float4*>(feat);

    float4 a0 = make_float4(0.f, 0.f, 0.f, 0.f);
    float4 a1 = make_float4(0.f, 0.f, 0.f, 0.f);
    int e = beg;
    for (; e + 4 <= end; e += 4) {
        int s0 = g_eidx[e], s1 = g_eidx[e + 1], s2 = g_eidx[e + 2], s3 = g_eidx[e + 3];
        float4 v0 = fp[(size_t)s0 * 32 + lane];
        float4 v1 = fp[(size_t)s1 * 32 + lane];
        float4 v2 = fp[(size_t)s2 * 32 + lane];
        float4 v3 = fp[(size_t)s3 * 32 + lane];
        a0.x += v0.x + v1.x; a0.y += v0.y + v1.y; a0.z += v0.z + v1.z; a0.w += v0.w + v1.w;
        a1.x += v2.x + v3.x; a1.y += v2.y + v3.y; a1.z += v2.z + v3.z; a1.w += v2.w + v3.w;
    }
    for (; e < end; e++) {
        int s0 = g_eidx[e];
        float4 v0 = fp[(size_t)s0 * 32 + lane];
        a0.x += v0.x; a0.y += v0.y; a0.z += v0.z; a0.w += v0.w;
    }
    a0.x += a1.x; a0.y += a1.y; a0.z += a1.z; a0.w += a1.w;

    float4 tv = reinterpret_cast<const float4*>(g_total)[lane];
    float4 h;
    h.x = tv.x - a0.x; h.y = tv.y - a0.y; h.z = tv.z - a0.z; h.w = tv.w - a0.w;
    float ss = h.x * h.x + h.y * h.y + h.z * h.z + h.w * h.w;
    #pragma unroll
    for (int o = 16; o; o >>= 1) ss += __shfl_xor_sync(0xffffffffu, ss, o);
    float inv = 1.f / fmaxf(sqrtf(ss), 1e-12f);
    h.x *= inv; h.y *= inv; h.z *= inv; h.w *= inv;
    reinterpret_cast<float4*>(g_h + (size_t)wid * D)[lane] = h;
}

// ---------------------------------------------------------------------------
// GEMM: out = g_h @ W^T + b, using packed fma.rn.f32x2 paired over k.
// 512 threads, 256x128 tile, 8x8 per thread (cols strided by 16).
// shW2[k2][c] holds pair (W[c][2k2], W[c][2k2+1]); acc lo/hi = even/odd k.
// ---------------------------------------------------------------------------
__global__ __launch_bounds__(512, 1)
void k_out(const float* __restrict__ W, const float* __restrict__ b,
           float* __restrict__ out, int N) {
    extern __shared__ float sh[];
    ull* shW2 = reinterpret_cast<ull*>(sh);        // [64][WP2] pairs
    float* shH = sh + 64 * WP2 * 2;                // [256][128]
    ull* shHu = reinterpret_cast<ull*>(shH);       // [256][64] pairs

    int tid = threadIdx.x;

    // Stage W pairs: shW2[k2*WP2 + c] = (W[c][2k2], W[c][2k2+1])
    const ull* Wu = reinterpret_cast<const ull*>(W);
    for (int idx = tid; idx < 64 * D; idx += 512) {
        int c  = idx >> 6;       // 0..127
        int k2 = idx & 63;       // 0..63  (consecutive -> coalesced gmem)
        shW2[k2 * WP2 + c] = Wu[c * 64 + k2];
    }

    int row0 = blockIdx.x * 256;
    // Stage H tile (zero-pad OOB rows)
    for (int idx = tid; idx < 256 * 32; idx += 512) {
        int r = idx >> 5, c4 = idx & 31;
        int row = row0 + r;
        float4 v = make_float4(0.f, 0.f, 0.f, 0.f);
        if (row < N) v = reinterpret_cast<const float4*>(g_h + (size_t)row * D)[c4];
        *reinterpret_cast<float4*>(shH + r * D + c4 * 4) = v;
    }
    __syncthreads();

    int tr = tid >> 4;       // 0..31 -> rows tr*8..+7
    int tc = tid & 15;       // cols tc + 16*j, j=0..7

    ull acc[8][8];
    #pragma unroll
    for (int i = 0; i < 8; i++)
        #pragma unroll
        for (int j = 0; j < 8; j++) acc[i][j] = 0ull;

    const ull* hbase = shHu + (tr << 3) * 64;
    const ull* wbase = shW2 + tc;

    #pragma unroll 2
    for (int k2 = 0; k2 < 64; k2++) {
        ull wv[8];
        #pragma unroll
        for (int j = 0; j < 8; j++) wv[j] = wbase[k2 * WP2 + 16 * j];
        #pragma unroll
        for (int i = 0; i < 8; i++) {
            ull hv = hbase[i * 64 + k2];
            #pragma unroll
            for (int j = 0; j < 8; j++)
                asm("fma.rn.f32x2 %0, %1, %2, %0;"
                    : "+l"(acc[i][j]) : "l"(hv), "l"(wv[j]));
        }
    }

    float bv[8];
    #pragma unroll
    for (int j = 0; j < 8; j++) bv[j] = b[tc + 16 * j];

    #pragma unroll
    for (int i = 0; i < 8; i++) {
        int row = row0 + (tr << 3) + i;
        if (row < N) {
            float* op = out + (size_t)row * D + tc;
            #pragma unroll
            for (int j = 0; j < 8; j++) {
                float lo = __uint_as_float((unsigned)(acc[i][j] & 0xffffffffu));
                float hi = __uint_as_float((unsigned)(acc[i][j] >> 32));
                op[16 * j] = lo + hi + bv[j];
            }
        }
    }
}

// ---------------------------------------------------------------------------
extern "C" void kernel_launch(void* const* d_in, const int* in_sizes, int n_in,
                              void* d_out, int out_size) {
    const float* feat = (const float*)d_in[0];
    const float* W    = (const float*)d_in[1];
    const float* b    = (const float*)d_in[2];
    const int*   src  = (const int*)d_in[3];
    const int*   dst  = (const int*)d_in[4];
    float*       out  = (float*)d_out;

    int N = in_sizes[0] / D;
    int E = in_sizes[3];
    int SB = (N + 1023) / 1024;

    k_init<<<(N + 255) / 256, 256>>>(N);
    k_total<<<1024, D>>>(feat, N);
    k_degree<<<(E + 255) / 256, 256>>>(dst, E);
    k_scan1<<<SB, 256>>>(N);
    k_scan2<<<1, 128>>>(SB, E, N);
    k_scan3<<<SB, 256>>>(N);
    k_fill<<<(E + 255) / 256, 256>>>(src, dst, E);
    k_gather<<<(N + 7) / 8, 256>>>(feat, N);

    size_t shbytes = (size_t)(64 * WP2 * 2 + 256 * D) * sizeof(float);
    cudaFuncSetAttribute(k_out, cudaFuncAttributeMaxDynamicSharedMemorySize, (int)shbytes);
    k_out<<<(N + 255) / 256, 512, shbytes>>>(W, b, out, N);
}

// round 4
// speedup vs baseline: 2.6502x; 2.6502x over previous
#include <cuda_runtime.h>

#define D 128
#define MAX_N 100000
#define MAX_E 1600000
#define WTP 132   // padded W^T row stride (floats); 66 ull per k row

typedef unsigned long long ull;

// Scratch (device globals — no allocations allowed)
__device__ float g_h[(size_t)MAX_N * D];     // normalized h rows
__device__ float g_total[D];
__device__ int   g_cnt[MAX_N];               // degrees, then fill cursor
__device__ int   g_off[MAX_N + 1];           // CSR offsets
__device__ int   g_eidx[MAX_E];              // src ids bucketed by dst
__device__ int   g_bsum[1024];               // scan block sums

// ---------------------------------------------------------------------------
__global__ void k_init(int N) {
    int i = blockIdx.x * blockDim.x + threadIdx.x;
    if (i < N) g_cnt[i] = 0;
    if (i < D) g_total[i] = 0.f;
}

// column sums: total[c] = sum_r feat[r][c]
__global__ void k_total(const float* __restrict__ feat, int N) {
    int c = threadIdx.x;
    float s = 0.f;
    for (int r = blockIdx.x; r < N; r += gridDim.x)
        s += feat[(size_t)r * D + c];
    atomicAdd(&g_total[c], s);
}

__global__ void k_degree(const int* __restrict__ dst, int E) {
    int e = blockIdx.x * blockDim.x + threadIdx.x;
    if (e < E) atomicAdd(&g_cnt[dst[e]], 1);
}

// scan1: per-1024-chunk sums
__global__ void k_scan1(int N) {
    __shared__ int ss[256];
    int base = blockIdx.x * 1024;
    int t = threadIdx.x;
    int s = 0;
    #pragma unroll
    for (int j = 0; j < 4; j++) {
        int i = base + t + j * 256;
        if (i < N) s += g_cnt[i];
    }
    ss[t] = s; __syncthreads();
    for (int o = 128; o; o >>= 1) { if (t < o) ss[t] += ss[t + o]; __syncthreads(); }
    if (t == 0) g_bsum[blockIdx.x] = ss[0];
}

// scan2: exclusive scan of block sums, plus g_off[N] = E
__global__ void k_scan2(int SB, int E, int N) {
    __shared__ int ss[1024];
    int t = threadIdx.x;
    for (int i = t; i < SB; i += blockDim.x) ss[i] = g_bsum[i];
    __syncthreads();
    if (t == 0) {
        int run = 0;
        for (int i = 0; i < SB; i++) { int v = ss[i]; ss[i] = run; run += v; }
        g_off[N] = E;
    }
    __syncthreads();
    for (int i = t; i < SB; i += blockDim.x) g_bsum[i] = ss[i];
}

// scan3: per-chunk exclusive scan + global base -> g_off, cursor init
__global__ void k_scan3(int N) {
    __shared__ int ss[256];
    int base = blockIdx.x * 1024;
    int t = threadIdx.x;
    int c[4]; int s = 0;
    #pragma unroll
    for (int j = 0; j < 4; j++) {
        int i = base + t * 4 + j;
        c[j] = (i < N) ? g_cnt[i] : 0;
        s += c[j];
    }
    ss[t] = s; __syncthreads();
    for (int o = 1; o < 256; o <<= 1) {
        int v = (t >= o) ? ss[t - o] : 0;
        __syncthreads();
        ss[t] += v;
        __syncthreads();
    }
    int run = g_bsum[blockIdx.x] + (ss[t] - s);
    #pragma unroll
    for (int j = 0; j < 4; j++) {
        int i = base + t * 4 + j;
        if (i < N) { g_off[i] = run; g_cnt[i] = run; }
        run += c[j];
    }
}

__global__ void k_fill(const int* __restrict__ src, const int* __restrict__ dst, int E) {
    int e = blockIdx.x * blockDim.x + threadIdx.x;
    if (e < E) {
        int pos = atomicAdd(&g_cnt[dst[e]], 1);
        g_eidx[pos] = src[e];
    }
}

// ---------------------------------------------------------------------------
// Gather + subtract + L2-normalize, fused. One warp per dst node.
// ---------------------------------------------------------------------------
__global__ void k_gather(const float* __restrict__ feat, int N) {
    int wid = (blockIdx.x * blockDim.x + threadIdx.x) >> 5;
    if (wid >= N) return;
    int lane = threadIdx.x & 31;
    int beg = g_off[wid], end = g_off[wid + 1];
    const float4* fp = reinterpret_cast<const float4*>(feat);

    float4 a0 = make_float4(0.f, 0.f, 0.f, 0.f);
    float4 a1 = make_float4(0.f, 0.f, 0.f, 0.f);
    int e = beg;
    for (; e + 4 <= end; e += 4) {
        int s0 = g_eidx[e], s1 = g_eidx[e + 1], s2 = g_eidx[e + 2], s3 = g_eidx[e + 3];
        float4 v0 = fp[(size_t)s0 * 32 + lane];
        float4 v1 = fp[(size_t)s1 * 32 + lane];
        float4 v2 = fp[(size_t)s2 * 32 + lane];
        float4 v3 = fp[(size_t)s3 * 32 + lane];
        a0.x += v0.x + v1.x; a0.y += v0.y + v1.y; a0.z += v0.z + v1.z; a0.w += v0.w + v1.w;
        a1.x += v2.x + v3.x; a1.y += v2.y + v3.y; a1.z += v2.z + v3.z; a1.w += v2.w + v3.w;
    }
    for (; e < end; e++) {
        int s0 = g_eidx[e];
        float4 v0 = fp[(size_t)s0 * 32 + lane];
        a0.x += v0.x; a0.y += v0.y; a0.z += v0.z; a0.w += v0.w;
    }
    a0.x += a1.x; a0.y += a1.y; a0.z += a1.z; a0.w += a1.w;

    float4 tv = reinterpret_cast<const float4*>(g_total)[lane];
    float4 h;
    h.x = tv.x - a0.x; h.y = tv.y - a0.y; h.z = tv.z - a0.z; h.w = tv.w - a0.w;
    float ss = h.x * h.x + h.y * h.y + h.z * h.z + h.w * h.w;
    #pragma unroll
    for (int o = 16; o; o >>= 1) ss += __shfl_xor_sync(0xffffffffu, ss, o);
    float inv = 1.f / fmaxf(sqrtf(ss), 1e-12f);
    h.x *= inv; h.y *= inv; h.z *= inv; h.w *= inv;
    reinterpret_cast<float4*>(g_h + (size_t)wid * D)[lane] = h;
}

// ---------------------------------------------------------------------------
// GEMM: out = g_h @ W^T + b.  fma.rn.f32x2 paired over OUTPUT COLUMNS.
// 512 threads, 256x128 tile, thread tile = 8 rows x 4 col-pairs (8 cols).
// Accumulator storage identical to scalar 8x8 (32 ull = 64 regs) -> no spill.
// shWT[k][c] = W[c][k]; col-pair (2p,2p+1) is a natural LDS.64.
// h broadcast scalar packed into both halves once per (row,k).
// shH rows skewed by (r>>3)*4 so the 2 rows read per warp differ in bank.
// ---------------------------------------------------------------------------
__global__ __launch_bounds__(512, 1)
void k_out(const float* __restrict__ W, const float* __restrict__ b,
           float* __restrict__ out, int N) {
    extern __shared__ float sh[];
    float* shWT = sh;                              // [D][WTP]
    float* shH  = sh + D * WTP;                    // [256][128] + skew 4/8rows
    const ull* shWTu = reinterpret_cast<const ull*>(shWT);

    int tid = threadIdx.x;

    // Stage W transposed: shWT[k*WTP + c] = W[c][k]
    for (int idx = tid; idx < D * D; idx += 512) {
        int c = idx >> 7;
        int k = idx & (D - 1);
        shWT[k * WTP + c] = W[idx];
    }

    int row0 = blockIdx.x * 256;
    // Stage H tile with skew (zero-pad OOB rows)
    for (int idx = tid; idx < 256 * 32; idx += 512) {
        int r = idx >> 5, c4 = idx & 31;
        int row = row0 + r;
        float4 v = make_float4(0.f, 0.f, 0.f, 0.f);
        if (row < N) v = reinterpret_cast<const float4*>(g_h + (size_t)row * D)[c4];
        *reinterpret_cast<float4*>(shH + r * D + (r >> 3) * 4 + c4 * 4) = v;
    }
    __syncthreads();

    int tr = tid >> 4;       // 0..31 -> rows tr*8..+7
    int tc = tid & 15;       // col-pairs tc + 16*j, j=0..3  (cols 2p, 2p+1)

    ull acc[8][4];
    #pragma unroll
    for (int i = 0; i < 8; i++)
        #pragma unroll
        for (int j = 0; j < 4; j++) acc[i][j] = 0ull;

    const float* hbase = shH + (tr << 3) * D + (tr << 2);   // skew = tr*4
    const ull* wbase = shWTu + tc;                          // + k*(WTP/2) + 16*j

    #pragma unroll 2
    for (int k = 0; k < D; k++) {
        ull wv[4];
        const ull* wrow = wbase + k * (WTP / 2);
        #pragma unroll
        for (int j = 0; j < 4; j++) wv[j] = wrow[16 * j];
        #pragma unroll
        for (int i = 0; i < 8; i++) {
            float hs = hbase[i * D + k];
            ull hd;
            asm("mov.b64 %0, {%1, %1};" : "=l"(hd) : "f"(hs));
            #pragma unroll
            for (int j = 0; j < 4; j++)
                asm("fma.rn.f32x2 %0, %1, %2, %0;"
                    : "+l"(acc[i][j]) : "l"(hd), "l"(wv[j]));
        }
    }

    // bias pairs
    float2 bv[4];
    #pragma unroll
    for (int j = 0; j < 4; j++)
        bv[j] = *reinterpret_cast<const float2*>(b + 2 * (tc + 16 * j));

    #pragma unroll
    for (int i = 0; i < 8; i++) {
        int row = row0 + (tr << 3) + i;
        if (row < N) {
            float* op = out + (size_t)row * D;
            #pragma unroll
            for (int j = 0; j < 4; j++) {
                float lo = __uint_as_float((unsigned)(acc[i][j] & 0xffffffffu));
                float hi = __uint_as_float((unsigned)(acc[i][j] >> 32));
                int c = 2 * (tc + 16 * j);
                *reinterpret_cast<float2*>(op + c) =
                    make_float2(lo + bv[j].x, hi + bv[j].y);
            }
        }
    }
}

// ---------------------------------------------------------------------------
extern "C" void kernel_launch(void* const* d_in, const int* in_sizes, int n_in,
                              void* d_out, int out_size) {
    const float* feat = (const float*)d_in[0];
    const float* W    = (const float*)d_in[1];
    const float* b    = (const float*)d_in[2];
    const int*   src  = (const int*)d_in[3];
    const int*   dst  = (const int*)d_in[4];
    float*       out  = (float*)d_out;

    int N = in_sizes[0] / D;
    int E = in_sizes[3];
    int SB = (N + 1023) / 1024;

    k_init<<<(N + 255) / 256, 256>>>(N);
    k_total<<<1024, D>>>(feat, N);
    k_degree<<<(E + 255) / 256, 256>>>(dst, E);
    k_scan1<<<SB, 256>>>(N);
    k_scan2<<<1, 128>>>(SB, E, N);
    k_scan3<<<SB, 256>>>(N);
    k_fill<<<(E + 255) / 256, 256>>>(src, dst, E);
    k_gather<<<(N + 7) / 8, 256>>>(feat, N);

    // smem: W^T [128][132] + H [256 rows][128 + skew] (skew adds 4 per 8 rows)
    size_t shbytes = (size_t)(D * WTP + 256 * D + 32 * 4) * sizeof(float);
    cudaFuncSetAttribute(k_out, cudaFuncAttributeMaxDynamicSharedMemorySize, (int)shbytes);
    k_out<<<(N + 255) / 256, 512, shbytes>>>(W, b, out, N);
}

// round 11
// speedup vs baseline: 2.7444x; 1.0356x over previous
#include <cuda_runtime.h>
#include <cuda_bf16.h>

#define D 128
#define MAX_N 100000
#define MAX_E 1600000
#define WTP 132   // padded W^T row stride (floats); 66 ull per k row

typedef unsigned long long ull;

// Scratch (device globals — no allocations allowed)
__device__ __nv_bfloat16 g_fb[(size_t)MAX_N * D];  // bf16 features
__device__ float g_h[(size_t)MAX_N * D];           // normalized h rows
__device__ float g_total[D];
__device__ int   g_cnt[MAX_N];                     // degrees, then fill cursor
__device__ int   g_off[MAX_N + 1];                 // CSR offsets
__device__ int   g_eidx[MAX_E];                    // src ids bucketed by dst
__device__ int   g_bsum[1024];                     // scan block sums

// ---------------------------------------------------------------------------
__global__ void k_init(int N) {
    int i = blockIdx.x * blockDim.x + threadIdx.x;
    if (i < N) g_cnt[i] = 0;
    if (i < D) g_total[i] = 0.f;
}

// column sums + bf16 conversion fused (one pass over features)
__global__ void k_total(const float* __restrict__ feat, int N) {
    int c = threadIdx.x;
    float s = 0.f;
    for (int r = blockIdx.x; r < N; r += gridDim.x) {
        float v = feat[(size_t)r * D + c];
        s += v;
        g_fb[(size_t)r * D + c] = __float2bfloat16(v);
    }
    atomicAdd(&g_total[c], s);
}

__global__ void k_degree(const int* __restrict__ dst, int E) {
    int e = blockIdx.x * blockDim.x + threadIdx.x;
    if (e < E) atomicAdd(&g_cnt[dst[e]], 1);
}

// scan1: per-1024-chunk sums
__global__ void k_scan1(int N) {
    __shared__ int ss[256];
    int base = blockIdx.x * 1024;
    int t = threadIdx.x;
    int s = 0;
    #pragma unroll
    for (int j = 0; j < 4; j++) {
        int i = base + t + j * 256;
        if (i < N) s += g_cnt[i];
    }
    ss[t] = s; __syncthreads();
    for (int o = 128; o; o >>= 1) { if (t < o) ss[t] += ss[t + o]; __syncthreads(); }
    if (t == 0) g_bsum[blockIdx.x] = ss[0];
}

// scan2: exclusive scan of block sums, plus g_off[N] = E
__global__ void k_scan2(int SB, int E, int N) {
    __shared__ int ss[1024];
    int t = threadIdx.x;
    for (int i = t; i < SB; i += blockDim.x) ss[i] = g_bsum[i];
    __syncthreads();
    if (t == 0) {
        int run = 0;
        for (int i = 0; i < SB; i++) { int v = ss[i]; ss[i] = run; run += v; }
        g_off[N] = E;
    }
    __syncthreads();
    for (int i = t; i < SB; i += blockDim.x) g_bsum[i] = ss[i];
}

// scan3: per-chunk exclusive scan + global base -> g_off, cursor init
__global__ void k_scan3(int N) {
    __shared__ int ss[256];
    int base = blockIdx.x * 1024;
    int t = threadIdx.x;
    int c[4]; int s = 0;
    #pragma unroll
    for (int j = 0; j < 4; j++) {
        int i = base + t * 4 + j;
        c[j] = (i < N) ? g_cnt[i] : 0;
        s += c[j];
    }
    ss[t] = s; __syncthreads();
    for (int o = 1; o < 256; o <<= 1) {
        int v = (t >= o) ? ss[t - o] : 0;
        __syncthreads();
        ss[t] += v;
        __syncthreads();
    }
    int run = g_bsum[blockIdx.x] + (ss[t] - s);
    #pragma unroll
    for (int j = 0; j < 4; j++) {
        int i = base + t * 4 + j;
        if (i < N) { g_off[i] = run; g_cnt[i] = run; }
        run += c[j];
    }
}

__global__ void k_fill(const int* __restrict__ src, const int* __restrict__ dst, int E) {
    int e = blockIdx.x * blockDim.x + threadIdx.x;
    if (e < E) {
        int pos = atomicAdd(&g_cnt[dst[e]], 1);
        g_eidx[pos] = src[e];
    }
}

// ---------------------------------------------------------------------------
// Gather (bf16 feats: half the L2 traffic) + subtract + L2-normalize, fused.
// One warp per dst node; lane owns cols 4*lane..4*lane+3 (8B bf16 load).
// ---------------------------------------------------------------------------
__global__ void k_gather(int N) {
    int wid = (blockIdx.x * blockDim.x + threadIdx.x) >> 5;
    if (wid >= N) return;
    int lane = threadIdx.x & 31;
    int beg = g_off[wid], end = g_off[wid + 1];

    float4 a0 = make_float4(0.f, 0.f, 0.f, 0.f);
    float4 a1 = make_float4(0.f, 0.f, 0.f, 0.f);
    int e = beg;
    for (; e + 4 <= end; e += 4) {
        int s0 = g_eidx[e], s1 = g_eidx[e + 1], s2 = g_eidx[e + 2], s3 = g_eidx[e + 3];
        ull p0 = *(const ull*)(g_fb + (size_t)s0 * D + lane * 4);
        ull p1 = *(const ull*)(g_fb + (size_t)s1 * D + lane * 4);
        ull p2 = *(const ull*)(g_fb + (size_t)s2 * D + lane * 4);
        ull p3 = *(const ull*)(g_fb + (size_t)s3 * D + lane * 4);
        {
            float2 f0 = __bfloat1622float2(*(__nv_bfloat162*)&p0);
            float2 f1 = __bfloat1622float2(*((__nv_bfloat162*)&p0 + 1));
            a0.x += f0.x; a0.y += f0.y; a0.z += f1.x; a0.w += f1.y;
        }
        {
            float2 f0 = __bfloat1622float2(*(__nv_bfloat162*)&p1);
            float2 f1 = __bfloat1622float2(*((__nv_bfloat162*)&p1 + 1));
            a1.x += f0.x; a1.y += f0.y; a1.z += f1.x; a1.w += f1.y;
        }
        {
            float2 f0 = __bfloat1622float2(*(__nv_bfloat162*)&p2);
            float2 f1 = __bfloat1622float2(*((__nv_bfloat162*)&p2 + 1));
            a0.x += f0.x; a0.y += f0.y; a0.z += f1.x; a0.w += f1.y;
        }
        {
            float2 f0 = __bfloat1622float2(*(__nv_bfloat162*)&p3);
            float2 f1 = __bfloat1622float2(*((__nv_bfloat162*)&p3 + 1));
            a1.x += f0.x; a1.y += f0.y; a1.z += f1.x; a1.w += f1.y;
        }
    }
    for (; e < end; e++) {
        int s0 = g_eidx[e];
        ull p0 = *(const ull*)(g_fb + (size_t)s0 * D + lane * 4);
        float2 f0 = __bfloat1622float2(*(__nv_bfloat162*)&p0);
        float2 f1 = __bfloat1622float2(*((__nv_bfloat162*)&p0 + 1));
        a0.x += f0.x; a0.y += f0.y; a0.z += f1.x; a0.w += f1.y;
    }
    a0.x += a1.x; a0.y += a1.y; a0.z += a1.z; a0.w += a1.w;

    float4 tv = reinterpret_cast<const float4*>(g_total)[lane];
    float4 h;
    h.x = tv.x - a0.x; h.y = tv.y - a0.y; h.z = tv.z - a0.z; h.w = tv.w - a0.w;
    float ss = h.x * h.x + h.y * h.y + h.z * h.z + h.w * h.w;
    #pragma unroll
    for (int o = 16; o; o >>= 1) ss += __shfl_xor_sync(0xffffffffu, ss, o);
    float inv = 1.f / fmaxf(sqrtf(ss), 1e-12f);
    h.x *= inv; h.y *= inv; h.z *= inv; h.w *= inv;
    reinterpret_cast<float4*>(g_h + (size_t)wid * D)[lane] = h;
}

// ---------------------------------------------------------------------------
// GEMM: out = g_h @ W^T + b.  fma.rn.f32x2 paired over OUTPUT COLUMNS.
// 512 threads, 256x128 tile, thread tile = 8 rows x 4 col-pairs (8 cols).
// ---------------------------------------------------------------------------
__global__ __launch_bounds__(512, 1)
void k_out(const float* __restrict__ W, const float* __restrict__ b,
           float* __restrict__ out, int N) {
    extern __shared__ float sh[];
    float* shWT = sh;                              // [D][WTP]
    float* shH  = sh + D * WTP;                    // [256][128] + skew 4/8rows
    const ull* shWTu = reinterpret_cast<const ull*>(shWT);

    int tid = threadIdx.x;

    // Stage W transposed: shWT[k*WTP + c] = W[c][k]
    for (int idx = tid; idx < D * D; idx += 512) {
        int c = idx >> 7;
        int k = idx & (D - 1);
        shWT[k * WTP + c] = W[idx];
    }

    int row0 = blockIdx.x * 256;
    // Stage H tile with skew (zero-pad OOB rows)
    for (int idx = tid; idx < 256 * 32; idx += 512) {
        int r = idx >> 5, c4 = idx & 31;
        int row = row0 + r;
        float4 v = make_float4(0.f, 0.f, 0.f, 0.f);
        if (row < N) v = reinterpret_cast<const float4*>(g_h + (size_t)row * D)[c4];
        *reinterpret_cast<float4*>(shH + r * D + (r >> 3) * 4 + c4 * 4) = v;
    }
    __syncthreads();

    int tr = tid >> 4;       // 0..31 -> rows tr*8..+7
    int tc = tid & 15;       // col-pairs tc + 16*j, j=0..3

    ull acc[8][4];
    #pragma unroll
    for (int i = 0; i < 8; i++)
        #pragma unroll
        for (int j = 0; j < 4; j++) acc[i][j] = 0ull;

    const float* hbase = shH + (tr << 3) * D + (tr << 2);   // skew = tr*4
    const ull* wbase = shWTu + tc;

    #pragma unroll 2
    for (int k = 0; k < D; k++) {
        ull wv[4];
        const ull* wrow = wbase + k * (WTP / 2);
        #pragma unroll
        for (int j = 0; j < 4; j++) wv[j] = wrow[16 * j];
        #pragma unroll
        for (int i = 0; i < 8; i++) {
            float hs = hbase[i * D + k];
            ull hd;
            asm("mov.b64 %0, {%1, %1};" : "=l"(hd) : "f"(hs));
            #pragma unroll
            for (int j = 0; j < 4; j++)
                asm("fma.rn.f32x2 %0, %1, %2, %0;"
                    : "+l"(acc[i][j]) : "l"(hd), "l"(wv[j]));
        }
    }

    float2 bv[4];
    #pragma unroll
    for (int j = 0; j < 4; j++)
        bv[j] = *reinterpret_cast<const float2*>(b + 2 * (tc + 16 * j));

    #pragma unroll
    for (int i = 0; i < 8; i++) {
        int row = row0 + (tr << 3) + i;
        if (row < N) {
            float* op = out + (size_t)row * D;
            #pragma unroll
            for (int j = 0; j < 4; j++) {
                float lo = __uint_as_float((unsigned)(acc[i][j] & 0xffffffffu));
                float hi = __uint_as_float((unsigned)(acc[i][j] >> 32));
                int c = 2 * (tc + 16 * j);
                *reinterpret_cast<float2*>(op + c) =
                    make_float2(lo + bv[j].x, hi + bv[j].y);
            }
        }
    }
}

// ---------------------------------------------------------------------------
extern "C" void kernel_launch(void* const* d_in, const int* in_sizes, int n_in,
                              void* d_out, int out_size) {
    const float* feat = (const float*)d_in[0];
    const float* W    = (const float*)d_in[1];
    const float* b    = (const float*)d_in[2];
    const int*   src  = (const int*)d_in[3];
    const int*   dst  = (const int*)d_in[4];
    float*       out  = (float*)d_out;

    int N = in_sizes[0] / D;
    int E = in_sizes[3];
    int SB = (N + 1023) / 1024;

    k_init<<<(N + 255) / 256, 256>>>(N);
    k_total<<<1024, D>>>(feat, N);
    k_degree<<<(E + 255) / 256, 256>>>(dst, E);
    k_scan1<<<SB, 256>>>(N);
    k_scan2<<<1, 128>>>(SB, E, N);
    k_scan3<<<SB, 256>>>(N);
    k_fill<<<(E + 255) / 256, 256>>>(src, dst, E);
    k_gather<<<(N + 7) / 8, 256>>>(N);

    size_t shbytes = (size_t)(D * WTP + 256 * D + 32 * 4) * sizeof(float);
    cudaFuncSetAttribute(k_out, cudaFuncAttributeMaxDynamicSharedMemorySize, (int)shbytes);
    k_out<<<(N + 255) / 256, 512, shbytes>>>(W, b, out, N);
}